// round 16
// baseline (speedup 1.0000x reference)
#include <cuda_runtime.h>
#include <cuda_fp16.h>
#include <cstdint>

#define NN 50000
#define EE 600000
#define HID 128
#define NC 21
#define SCAN_T 512
#define NB ((NN + SCAN_T - 1) / SCAN_T)   // 98

// pipeline split: GEMM blocks of 128 rows; 196 blocks = nodes [0, 25088)
#define GEMM_BLOCKS 391
#define GEMM_LO 196
#define NODE_SPLIT (GEMM_LO * 128)        // 25088

// ---------------- scratch (__device__ globals; no cudaMalloc allowed) ------
__device__ __align__(16) __half g_h[NN * HID];    // GEMM output (fp16)
__device__ __align__(16) __half g_a2[NN * HID];   // conv1 output (fp16)
__device__ float g_dinv[NN];
__device__ int   g_cnt[NN];        // zeroed by scan after use (and statically)
__device__ int   g_cur[NN];        // set to row start by scan each call
__device__ int   g_row[NN + 1];    // CSR row starts; row[NN] = EE
__device__ int   g_bval[NB];       // scan block aggregates
__device__ int   g_bflag[NB];      // scan publish flags
__device__ __align__(8) uint2 g_edge[EE];  // (src, weight-bits) per CSR slot

// ---------------- degree count: 4 edges per thread (int4) ----------------
__global__ void k_deg_count(const int* __restrict__ ei) {
    if (blockIdx.x == 0 && threadIdx.x < NB) g_bflag[threadIdx.x] = 0;
    int t = blockIdx.x * blockDim.x + threadIdx.x;
    if (t * 4 >= EE) return;
    int4 d = *reinterpret_cast<const int4*>(ei + EE + t * 4);
    atomicAdd(&g_cnt[d.x], 1);
    atomicAdd(&g_cnt[d.y], 1);
    atomicAdd(&g_cnt[d.z], 1);
    atomicAdd(&g_cnt[d.w], 1);
}

// ---------------- single-pass scan (decoupled lookback) --------------------
__global__ void k_scan() {
    __shared__ int wsum[16];
    __shared__ int sprefix;
    int lane = threadIdx.x & 31;
    int wid = threadIdx.x >> 5;
    int gid = blockIdx.x * SCAN_T + threadIdx.x;
    int c = (gid < NN) ? g_cnt[gid] : 0;

    int incl = c;
#pragma unroll
    for (int off = 1; off < 32; off <<= 1) {
        int t = __shfl_up_sync(0xffffffffu, incl, off);
        if (lane >= off) incl += t;
    }
    if (lane == 31) wsum[wid] = incl;
    __syncthreads();
    if (wid == 0) {
        int s = (lane < 16) ? wsum[lane] : 0;
#pragma unroll
        for (int off = 1; off < 16; off <<= 1) {
            int t = __shfl_up_sync(0xffffffffu, s, off);
            if (lane >= off) s += t;
        }
        if (lane < 16) wsum[lane] = s;
    }
    __syncthreads();
    int wpre = (wid > 0) ? wsum[wid - 1] : 0;
    int inclFull = incl + wpre;

    if (threadIdx.x == SCAN_T - 1) {
        g_bval[blockIdx.x] = inclFull;
        __threadfence();
        g_bflag[blockIdx.x] = 1;
    }

    if (threadIdx.x == 0) sprefix = 0;
    if (wid == 0 && blockIdx.x > 0) {
        int acc = 0;
        for (int j = lane; j < (int)blockIdx.x; j += 32) {
            while (((volatile int*)g_bflag)[j] == 0) {}
            acc += ((volatile int*)g_bval)[j];
        }
#pragma unroll
        for (int off = 16; off; off >>= 1)
            acc += __shfl_xor_sync(0xffffffffu, acc, off);
        if (lane == 0) sprefix = acc;
    }
    __syncthreads();

    if (gid < NN) {
        int start = inclFull - c + sprefix;
        g_row[gid] = start;
        g_cur[gid] = start;
        g_dinv[gid] = rsqrtf((float)(c + 1));
        g_cnt[gid] = 0;
    }
    if (blockIdx.x == NB - 1 && threadIdx.x == SCAN_T - 1) g_row[NN] = EE;
}

// ---------------- bin edges: 4/thread; dinv loads hoisted before atomics ---
__global__ void k_bin(const int* __restrict__ ei) {
    int t = blockIdx.x * blockDim.x + threadIdx.x;
    if (t * 4 >= EE) return;
    int4 sv = *reinterpret_cast<const int4*>(ei + t * 4);
    int4 dv = *reinterpret_cast<const int4*>(ei + EE + t * 4);
    int s[4] = {sv.x, sv.y, sv.z, sv.w};
    int d[4] = {dv.x, dv.y, dv.z, dv.w};
    float w[4];
#pragma unroll
    for (int q = 0; q < 4; q++) w[q] = __ldg(&g_dinv[s[q]]) * __ldg(&g_dinv[d[q]]);
    int pos[4];
#pragma unroll
    for (int q = 0; q < 4; q++) pos[q] = atomicAdd(&g_cur[d[q]], 1);
#pragma unroll
    for (int q = 0; q < 4; q++)
        g_edge[pos[q]] = make_uint2((unsigned)s[q], __float_as_uint(w[q]));
}

// ---------------- fp16 tensor-core GEMM (block-offset aware) ---------------
#define BM 128
#define KC2 64
#define SAH 72
#define SWN 136

__device__ __forceinline__ uint32_t h2_pack(float a, float b) {
    __half2 h = __floats2half2_rn(a, b);
    return *reinterpret_cast<uint32_t*>(&h);
}

__device__ __forceinline__ void mma_fp16(float* d, const uint32_t* a, const uint32_t* b) {
    asm volatile(
        "mma.sync.aligned.m16n8k16.row.col.f32.f16.f16.f32 "
        "{%0,%1,%2,%3}, {%4,%5,%6,%7}, {%8,%9}, {%0,%1,%2,%3};"
        : "+f"(d[0]), "+f"(d[1]), "+f"(d[2]), "+f"(d[3])
        : "r"(a[0]), "r"(a[1]), "r"(a[2]), "r"(a[3]), "r"(b[0]), "r"(b[1]));
}

__global__ __launch_bounds__(256) void k_gemm_fp16(const float* __restrict__ A,
                                                   const float* __restrict__ W,
                                                   int bOff) {
    __shared__ __half sA[BM * SAH];
    __shared__ __half sW[KC2 * SWN];

    const int tid  = threadIdx.x;
    const int lane = tid & 31;
    const int warp = tid >> 5;
    const int wm = warp >> 1;
    const int wn = warp & 1;
    const int gid = lane >> 2;
    const int tig = lane & 3;
    const int rowBase = (blockIdx.x + bOff) * BM;

    float acc[2][8][4];
#pragma unroll
    for (int mt = 0; mt < 2; mt++)
#pragma unroll
        for (int nt = 0; nt < 8; nt++)
#pragma unroll
            for (int q = 0; q < 4; q++) acc[mt][nt][q] = 0.f;

    for (int kc = 0; kc < HID; kc += KC2) {
        __syncthreads();
#pragma unroll
        for (int i = 0; i < 8; i++) {
            int idx = i * 256 + tid;
            int r = idx >> 5, cq = idx & 31;
            float4 v = *reinterpret_cast<const float4*>(W + (kc + r) * HID + cq * 4);
            *reinterpret_cast<uint2*>(&sW[r * SWN + cq * 4]) =
                make_uint2(h2_pack(v.x, v.y), h2_pack(v.z, v.w));
        }
        if (A) {
#pragma unroll
            for (int i = 0; i < 8; i++) {
                int idx = i * 256 + tid;
                int r = idx >> 4, kq = idx & 15;
                int grow = rowBase + r;
                float4 v = (grow < NN)
                    ? *reinterpret_cast<const float4*>(A + grow * HID + kc + kq * 4)
                    : make_float4(0.f, 0.f, 0.f, 0.f);
                *reinterpret_cast<uint2*>(&sA[r * SAH + kq * 4]) =
                    make_uint2(h2_pack(v.x, v.y), h2_pack(v.z, v.w));
            }
        } else {
#pragma unroll
            for (int i = 0; i < 4; i++) {
                int idx = i * 256 + tid;
                int r = idx >> 3, kq = idx & 7;
                int grow = rowBase + r;
                uint4 v = (grow < NN)
                    ? *reinterpret_cast<const uint4*>(g_a2 + grow * HID + kc + kq * 8)
                    : make_uint4(0u, 0u, 0u, 0u);
                *reinterpret_cast<uint4*>(&sA[r * SAH + kq * 8]) = v;
            }
        }
        __syncthreads();

        const unsigned short* sWu = reinterpret_cast<const unsigned short*>(sW);
#pragma unroll
        for (int ks = 0; ks < 4; ks++) {
            int k0 = ks * 16;
            uint32_t a[2][4];
#pragma unroll
            for (int mt = 0; mt < 2; mt++) {
                int r0 = wm * 32 + mt * 16;
                a[mt][0] = *reinterpret_cast<const uint32_t*>(&sA[(r0 + gid) * SAH + k0 + 2 * tig]);
                a[mt][1] = *reinterpret_cast<const uint32_t*>(&sA[(r0 + gid + 8) * SAH + k0 + 2 * tig]);
                a[mt][2] = *reinterpret_cast<const uint32_t*>(&sA[(r0 + gid) * SAH + k0 + 2 * tig + 8]);
                a[mt][3] = *reinterpret_cast<const uint32_t*>(&sA[(r0 + gid + 8) * SAH + k0 + 2 * tig + 8]);
            }
#pragma unroll
            for (int nt = 0; nt < 8; nt++) {
                int c0 = wn * 64 + nt * 8 + gid;
                uint32_t w00 = sWu[(k0 + 2 * tig)     * SWN + c0];
                uint32_t w01 = sWu[(k0 + 2 * tig + 1) * SWN + c0];
                uint32_t w10 = sWu[(k0 + 2 * tig + 8) * SWN + c0];
                uint32_t w11 = sWu[(k0 + 2 * tig + 9) * SWN + c0];
                uint32_t b[2];
                b[0] = w00 | (w01 << 16);
                b[1] = w10 | (w11 << 16);
                mma_fp16(acc[0][nt], a[0], b);
                mma_fp16(acc[1][nt], a[1], b);
            }
        }
    }

    __half2* h2 = reinterpret_cast<__half2*>(g_h);
#pragma unroll
    for (int mt = 0; mt < 2; mt++) {
        int r0 = rowBase + wm * 32 + mt * 16 + gid;
#pragma unroll
        for (int half_ = 0; half_ < 2; half_++) {
            int row = r0 + half_ * 8;
            if (row < NN) {
#pragma unroll
                for (int nt = 0; nt < 8; nt++) {
                    int col = wn * 64 + nt * 8 + tig * 2;
                    h2[row * 64 + (col >> 1)] =
                        __floats2half2_rn(acc[mt][nt][half_ * 2], acc[mt][nt][half_ * 2 + 1]);
                }
            }
        }
    }
}

// ---------------- gather core: 4-way unrolled edge loop --------------------
__device__ __forceinline__ float4 gather_node(int node, int lane,
                                              const float* __restrict__ b) {
    const uint2* h4 = reinterpret_cast<const uint2*>(g_h);
    float dn = g_dinv[node];
    float dd = dn * dn;

    uint2 u = h4[node * 32 + lane];
    float2 f0 = __half22float2(*reinterpret_cast<__half2*>(&u.x));
    float2 f1 = __half22float2(*reinterpret_cast<__half2*>(&u.y));
    float4 acc = make_float4(f0.x * dd, f0.y * dd, f1.x * dd, f1.y * dd);

    int beg = g_row[node];
    int cnt = g_row[node + 1] - beg;
    for (int j0 = 0; j0 < cnt; j0 += 32) {
        int n = min(32, cnt - j0);
        int s = 0; float w = 0.f;
        if (lane < n) {
            uint2 ew = g_edge[beg + j0 + lane];
            s = (int)ew.x;
            w = __uint_as_float(ew.y);
        }
        for (int i = 0; i < n; i += 4) {
            uint2 uv[4]; float wv[4];
#pragma unroll
            for (int j = 0; j < 4; j++) {
                int   si = __shfl_sync(0xffffffffu, s, (i + j) & 31);
                wv[j] = __shfl_sync(0xffffffffu, w, (i + j) & 31);
                if (i + j >= n) wv[j] = 0.f;
                uv[j] = h4[si * 32 + lane];
            }
#pragma unroll
            for (int j = 0; j < 4; j++) {
                float2 v0 = __half22float2(*reinterpret_cast<__half2*>(&uv[j].x));
                float2 v1 = __half22float2(*reinterpret_cast<__half2*>(&uv[j].y));
                acc.x += v0.x * wv[j]; acc.y += v0.y * wv[j];
                acc.z += v1.x * wv[j]; acc.w += v1.y * wv[j];
            }
        }
    }

    float4 bb = reinterpret_cast<const float4*>(b)[lane];
    acc.x = fmaxf(acc.x + bb.x, 0.f);
    acc.y = fmaxf(acc.y + bb.y, 0.f);
    acc.z = fmaxf(acc.z + bb.z, 0.f);
    acc.w = fmaxf(acc.w + bb.w, 0.f);
    return acc;
}

// ---------------- gather1: writes g_a2 (fp16); node-range aware ------------
__global__ void k_gather(const float* __restrict__ b, int nodeOff, int nodeEnd) {
    const int lane = threadIdx.x & 31;
    int node = nodeOff + blockIdx.x * (blockDim.x >> 5) + (threadIdx.x >> 5);
    if (node >= nodeEnd) return;
    float4 acc = gather_node(node, lane, b);
    reinterpret_cast<uint2*>(g_a2)[node * 32 + lane] =
        make_uint2(h2_pack(acc.x, acc.y), h2_pack(acc.z, acc.w));
}

// ---------------- gather2 + FC fused: writes logits directly ----------------
__global__ void k_gather_fc(const float* __restrict__ b,
                            const float* __restrict__ Wfc,
                            const float* __restrict__ bfc,
                            float* __restrict__ out) {
    __shared__ float WsT[NC * HID];
    __shared__ float bs[NC];
    for (int i = threadIdx.x; i < NC * HID; i += blockDim.x) {
        int c = i >> 7;
        int k = i & 127;
        WsT[i] = Wfc[k * NC + c];
    }
    if (threadIdx.x < NC) bs[threadIdx.x] = bfc[threadIdx.x];
    __syncthreads();

    const int lane = threadIdx.x & 31;
    int node = blockIdx.x * (blockDim.x >> 5) + (threadIdx.x >> 5);
    if (node >= NN) return;
    float4 a = gather_node(node, lane, b);

#pragma unroll
    for (int c = 0; c < NC; c++) {
        const float4 w = reinterpret_cast<const float4*>(WsT + c * HID)[lane];
        float p = a.x * w.x + a.y * w.y + a.z * w.z + a.w * w.w;
        p += __shfl_xor_sync(0xffffffffu, p, 16);
        p += __shfl_xor_sync(0xffffffffu, p, 8);
        p += __shfl_xor_sync(0xffffffffu, p, 4);
        p += __shfl_xor_sync(0xffffffffu, p, 2);
        p += __shfl_xor_sync(0xffffffffu, p, 1);
        if (lane == 0) out[node * NC + c] = p + bs[c];
    }
}

// ---------------- launch ----------------
extern "C" void kernel_launch(void* const* d_in, const int* in_sizes, int n_in,
                              void* d_out, int out_size) {
    const float* x  = (const float*)d_in[0];
    const int* ei   = (const int*)d_in[1];   // int32 (JAX x64 disabled)
    const float* W1 = (const float*)d_in[2];
    const float* b1 = (const float*)d_in[3];
    const float* W2 = (const float*)d_in[4];
    const float* b2 = (const float*)d_in[5];
    const float* Wfc = (const float*)d_in[6];
    const float* bfc = (const float*)d_in[7];
    float* out = (float*)d_out;

    static cudaStream_t s2 = nullptr;
    static cudaEvent_t evFork = nullptr, evJoin = nullptr, evG1lo = nullptr, evGemm2lo = nullptr;
    if (!s2) {
        cudaStreamCreate(&s2);
        cudaEventCreateWithFlags(&evFork, cudaEventDisableTiming);
        cudaEventCreateWithFlags(&evJoin, cudaEventDisableTiming);
        cudaEventCreateWithFlags(&evG1lo, cudaEventDisableTiming);
        cudaEventCreateWithFlags(&evGemm2lo, cudaEventDisableTiming);
    }

    const int T = 256;
    const int eBlk4 = (EE / 4 + T - 1) / T;
    const int g1loBlk = NODE_SPLIT / 8;                    // 3136 (nodes [0, 25088))
    const int g1hiBlk = (NN - NODE_SPLIT + 7) / 8;         // nodes [25088, NN)
    const int fcBlk   = (NN + 7) / 8;

    // fork: GEMM1 (independent of graph structure) on side stream
    cudaEventRecord(evFork, 0);
    cudaStreamWaitEvent(s2, evFork, 0);
    k_gemm_fp16<<<GEMM_BLOCKS, 256, 0, s2>>>(x, W1, 0);

    // CSR build chain on main stream (concurrent with GEMM1)
    k_deg_count<<<eBlk4, T>>>(ei);
    k_scan<<<NB, SCAN_T>>>();
    k_bin<<<eBlk4, T>>>(ei);

    // join: gather1 needs GEMM1 + CSR
    cudaEventRecord(evJoin, s2);
    cudaStreamWaitEvent(0, evJoin, 0);

    // pipelined conv1-aggregate / GEMM2:
    //   main: gather1_lo -> gather1_hi -> gemm2_hi
    //   s2:                 gemm2_lo (overlaps gather1_hi)
    k_gather<<<g1loBlk, T>>>(b1, 0, NODE_SPLIT);
    cudaEventRecord(evG1lo, 0);
    cudaStreamWaitEvent(s2, evG1lo, 0);
    k_gemm_fp16<<<GEMM_LO, 256, 0, s2>>>(nullptr, W2, 0);
    k_gather<<<g1hiBlk, T>>>(b1, NODE_SPLIT, NN);
    k_gemm_fp16<<<GEMM_BLOCKS - GEMM_LO, 256>>>(nullptr, W2, GEMM_LO);

    // join gemm2_lo before fused conv2-aggregate+FC
    cudaEventRecord(evGemm2lo, s2);
    cudaStreamWaitEvent(0, evGemm2lo, 0);
    k_gather_fc<<<fcBlk, T>>>(b2, Wfc, bfc, out);
}

// round 17
// speedup vs baseline: 1.0033x; 1.0033x over previous
#include <cuda_runtime.h>
#include <cuda_fp16.h>
#include <cstdint>

#define NN 50000
#define EE 600000
#define HID 128
#define NC 21
#define SCAN_T 512
#define NB ((NN + SCAN_T - 1) / SCAN_T)   // 98

// ---------------- scratch (__device__ globals; no cudaMalloc allowed) ------
__device__ __align__(16) __half g_h[NN * HID];    // GEMM output (fp16)
__device__ __align__(16) __half g_a2[NN * HID];   // conv1 output (fp16)
__device__ float g_dinv[NN];
__device__ int   g_cnt[NN];        // zeroed by scan after use (and statically)
__device__ int   g_cur[NN];        // set to row start by scan each call
__device__ int   g_row[NN + 1];    // CSR row starts; row[NN] = EE
__device__ int   g_bval[NB];       // scan block aggregates
__device__ int   g_bflag[NB];      // scan publish flags
__device__ __align__(8) uint2 g_edge[EE];  // (src, weight-bits) per CSR slot

// ---------------- degree count: 2 edges per thread (int2) ------------------
// more resident warps -> more atomic chains in flight per SM
__global__ void k_deg_count(const int* __restrict__ ei) {
    if (blockIdx.x == 0 && threadIdx.x < NB) g_bflag[threadIdx.x] = 0;
    int t = blockIdx.x * blockDim.x + threadIdx.x;
    if (t * 2 >= EE) return;
    int2 d = *reinterpret_cast<const int2*>(ei + EE + t * 2);
    atomicAdd(&g_cnt[d.x], 1);
    atomicAdd(&g_cnt[d.y], 1);
}

// ---------------- single-pass scan (decoupled lookback) --------------------
// computes g_row (exclusive), g_cur (= row start), g_dinv; zeroes g_cnt
__global__ void k_scan() {
    __shared__ int wsum[16];
    __shared__ int sprefix;
    int lane = threadIdx.x & 31;
    int wid = threadIdx.x >> 5;
    int gid = blockIdx.x * SCAN_T + threadIdx.x;
    int c = (gid < NN) ? g_cnt[gid] : 0;

    int incl = c;
#pragma unroll
    for (int off = 1; off < 32; off <<= 1) {
        int t = __shfl_up_sync(0xffffffffu, incl, off);
        if (lane >= off) incl += t;
    }
    if (lane == 31) wsum[wid] = incl;
    __syncthreads();
    if (wid == 0) {
        int s = (lane < 16) ? wsum[lane] : 0;
#pragma unroll
        for (int off = 1; off < 16; off <<= 1) {
            int t = __shfl_up_sync(0xffffffffu, s, off);
            if (lane >= off) s += t;
        }
        if (lane < 16) wsum[lane] = s;
    }
    __syncthreads();
    int wpre = (wid > 0) ? wsum[wid - 1] : 0;
    int inclFull = incl + wpre;

    if (threadIdx.x == SCAN_T - 1) {
        g_bval[blockIdx.x] = inclFull;
        __threadfence();
        g_bflag[blockIdx.x] = 1;
    }

    if (threadIdx.x == 0) sprefix = 0;
    if (wid == 0 && blockIdx.x > 0) {
        int acc = 0;
        for (int j = lane; j < (int)blockIdx.x; j += 32) {
            while (((volatile int*)g_bflag)[j] == 0) {}
            acc += ((volatile int*)g_bval)[j];
        }
#pragma unroll
        for (int off = 16; off; off >>= 1)
            acc += __shfl_xor_sync(0xffffffffu, acc, off);
        if (lane == 0) sprefix = acc;
    }
    __syncthreads();

    if (gid < NN) {
        int start = inclFull - c + sprefix;
        g_row[gid] = start;
        g_cur[gid] = start;
        g_dinv[gid] = rsqrtf((float)(c + 1));
        g_cnt[gid] = 0;
    }
    if (blockIdx.x == NB - 1 && threadIdx.x == SCAN_T - 1) g_row[NN] = EE;
}

// ---------------- bin edges: 2/thread; dinv loads hoisted before atomics ---
__global__ void k_bin(const int* __restrict__ ei) {
    int t = blockIdx.x * blockDim.x + threadIdx.x;
    if (t * 2 >= EE) return;
    int2 sv = *reinterpret_cast<const int2*>(ei + t * 2);
    int2 dv = *reinterpret_cast<const int2*>(ei + EE + t * 2);
    int s[2] = {sv.x, sv.y};
    int d[2] = {dv.x, dv.y};
    float w[2];
#pragma unroll
    for (int q = 0; q < 2; q++) w[q] = __ldg(&g_dinv[s[q]]) * __ldg(&g_dinv[d[q]]);
    int pos[2];
#pragma unroll
    for (int q = 0; q < 2; q++) pos[q] = atomicAdd(&g_cur[d[q]], 1);
#pragma unroll
    for (int q = 0; q < 2; q++)
        g_edge[pos[q]] = make_uint2((unsigned)s[q], __float_as_uint(w[q]));
}

// ---------------- fp16 tensor-core GEMM: g_h = fp16(A) @ fp16(W) -----------
#define BM 128
#define KC2 64
#define SAH 72    // halves per A row  (64 + 8)
#define SWN 136   // halves per W row  (128 + 8)

__device__ __forceinline__ uint32_t h2_pack(float a, float b) {
    __half2 h = __floats2half2_rn(a, b);
    return *reinterpret_cast<uint32_t*>(&h);
}

__device__ __forceinline__ void mma_fp16(float* d, const uint32_t* a, const uint32_t* b) {
    asm volatile(
        "mma.sync.aligned.m16n8k16.row.col.f32.f16.f16.f32 "
        "{%0,%1,%2,%3}, {%4,%5,%6,%7}, {%8,%9}, {%0,%1,%2,%3};"
        : "+f"(d[0]), "+f"(d[1]), "+f"(d[2]), "+f"(d[3])
        : "r"(a[0]), "r"(a[1]), "r"(a[2]), "r"(a[3]), "r"(b[0]), "r"(b[1]));
}

__global__ __launch_bounds__(256) void k_gemm_fp16(const float* __restrict__ A,
                                                   const float* __restrict__ W) {
    __shared__ __half sA[BM * SAH];
    __shared__ __half sW[KC2 * SWN];

    const int tid  = threadIdx.x;
    const int lane = tid & 31;
    const int warp = tid >> 5;
    const int wm = warp >> 1;
    const int wn = warp & 1;
    const int gid = lane >> 2;
    const int tig = lane & 3;
    const int rowBase = blockIdx.x * BM;

    float acc[2][8][4];
#pragma unroll
    for (int mt = 0; mt < 2; mt++)
#pragma unroll
        for (int nt = 0; nt < 8; nt++)
#pragma unroll
            for (int q = 0; q < 4; q++) acc[mt][nt][q] = 0.f;

    for (int kc = 0; kc < HID; kc += KC2) {
        __syncthreads();
#pragma unroll
        for (int i = 0; i < 8; i++) {
            int idx = i * 256 + tid;
            int r = idx >> 5, cq = idx & 31;
            float4 v = *reinterpret_cast<const float4*>(W + (kc + r) * HID + cq * 4);
            *reinterpret_cast<uint2*>(&sW[r * SWN + cq * 4]) =
                make_uint2(h2_pack(v.x, v.y), h2_pack(v.z, v.w));
        }
        if (A) {
#pragma unroll
            for (int i = 0; i < 8; i++) {
                int idx = i * 256 + tid;
                int r = idx >> 4, kq = idx & 15;
                int grow = rowBase + r;
                float4 v = (grow < NN)
                    ? *reinterpret_cast<const float4*>(A + grow * HID + kc + kq * 4)
                    : make_float4(0.f, 0.f, 0.f, 0.f);
                *reinterpret_cast<uint2*>(&sA[r * SAH + kq * 4]) =
                    make_uint2(h2_pack(v.x, v.y), h2_pack(v.z, v.w));
            }
        } else {
#pragma unroll
            for (int i = 0; i < 4; i++) {
                int idx = i * 256 + tid;
                int r = idx >> 3, kq = idx & 7;
                int grow = rowBase + r;
                uint4 v = (grow < NN)
                    ? *reinterpret_cast<const uint4*>(g_a2 + grow * HID + kc + kq * 8)
                    : make_uint4(0u, 0u, 0u, 0u);
                *reinterpret_cast<uint4*>(&sA[r * SAH + kq * 8]) = v;
            }
        }
        __syncthreads();

        const unsigned short* sWu = reinterpret_cast<const unsigned short*>(sW);
#pragma unroll
        for (int ks = 0; ks < 4; ks++) {
            int k0 = ks * 16;
            uint32_t a[2][4];
#pragma unroll
            for (int mt = 0; mt < 2; mt++) {
                int r0 = wm * 32 + mt * 16;
                a[mt][0] = *reinterpret_cast<const uint32_t*>(&sA[(r0 + gid) * SAH + k0 + 2 * tig]);
                a[mt][1] = *reinterpret_cast<const uint32_t*>(&sA[(r0 + gid + 8) * SAH + k0 + 2 * tig]);
                a[mt][2] = *reinterpret_cast<const uint32_t*>(&sA[(r0 + gid) * SAH + k0 + 2 * tig + 8]);
                a[mt][3] = *reinterpret_cast<const uint32_t*>(&sA[(r0 + gid + 8) * SAH + k0 + 2 * tig + 8]);
            }
#pragma unroll
            for (int nt = 0; nt < 8; nt++) {
                int c0 = wn * 64 + nt * 8 + gid;
                uint32_t w00 = sWu[(k0 + 2 * tig)     * SWN + c0];
                uint32_t w01 = sWu[(k0 + 2 * tig + 1) * SWN + c0];
                uint32_t w10 = sWu[(k0 + 2 * tig + 8) * SWN + c0];
                uint32_t w11 = sWu[(k0 + 2 * tig + 9) * SWN + c0];
                uint32_t b[2];
                b[0] = w00 | (w01 << 16);
                b[1] = w10 | (w11 << 16);
                mma_fp16(acc[0][nt], a[0], b);
                mma_fp16(acc[1][nt], a[1], b);
            }
        }
    }

    __half2* h2 = reinterpret_cast<__half2*>(g_h);
#pragma unroll
    for (int mt = 0; mt < 2; mt++) {
        int r0 = rowBase + wm * 32 + mt * 16 + gid;
#pragma unroll
        for (int half_ = 0; half_ < 2; half_++) {
            int row = r0 + half_ * 8;
            if (row < NN) {
#pragma unroll
                for (int nt = 0; nt < 8; nt++) {
                    int col = wn * 64 + nt * 8 + tig * 2;
                    h2[row * 64 + (col >> 1)] =
                        __floats2half2_rn(acc[mt][nt][half_ * 2], acc[mt][nt][half_ * 2 + 1]);
                }
            }
        }
    }
}

// ---------------- gather core: 4-way unrolled edge loop --------------------
__device__ __forceinline__ float4 gather_node(int node, int lane,
                                              const float* __restrict__ b) {
    const uint2* h4 = reinterpret_cast<const uint2*>(g_h);
    float dn = g_dinv[node];
    float dd = dn * dn;

    uint2 u = h4[node * 32 + lane];
    float2 f0 = __half22float2(*reinterpret_cast<__half2*>(&u.x));
    float2 f1 = __half22float2(*reinterpret_cast<__half2*>(&u.y));
    float4 acc = make_float4(f0.x * dd, f0.y * dd, f1.x * dd, f1.y * dd);

    int beg = g_row[node];
    int cnt = g_row[node + 1] - beg;
    for (int j0 = 0; j0 < cnt; j0 += 32) {
        int n = min(32, cnt - j0);
        int s = 0; float w = 0.f;
        if (lane < n) {
            uint2 ew = g_edge[beg + j0 + lane];
            s = (int)ew.x;
            w = __uint_as_float(ew.y);
        }
        for (int i = 0; i < n; i += 4) {
            uint2 uv[4]; float wv[4];
#pragma unroll
            for (int j = 0; j < 4; j++) {
                int   si = __shfl_sync(0xffffffffu, s, (i + j) & 31);
                wv[j] = __shfl_sync(0xffffffffu, w, (i + j) & 31);
                if (i + j >= n) wv[j] = 0.f;
                uv[j] = h4[si * 32 + lane];
            }
#pragma unroll
            for (int j = 0; j < 4; j++) {
                float2 v0 = __half22float2(*reinterpret_cast<__half2*>(&uv[j].x));
                float2 v1 = __half22float2(*reinterpret_cast<__half2*>(&uv[j].y));
                acc.x += v0.x * wv[j]; acc.y += v0.y * wv[j];
                acc.z += v1.x * wv[j]; acc.w += v1.y * wv[j];
            }
        }
    }

    float4 bb = reinterpret_cast<const float4*>(b)[lane];
    acc.x = fmaxf(acc.x + bb.x, 0.f);
    acc.y = fmaxf(acc.y + bb.y, 0.f);
    acc.z = fmaxf(acc.z + bb.z, 0.f);
    acc.w = fmaxf(acc.w + bb.w, 0.f);
    return acc;
}

// ---------------- gather1: writes g_a2 (fp16) ----------------
__global__ void k_gather(const float* __restrict__ b) {
    const int lane = threadIdx.x & 31;
    int node = blockIdx.x * (blockDim.x >> 5) + (threadIdx.x >> 5);
    if (node >= NN) return;
    float4 acc = gather_node(node, lane, b);
    reinterpret_cast<uint2*>(g_a2)[node * 32 + lane] =
        make_uint2(h2_pack(acc.x, acc.y), h2_pack(acc.z, acc.w));
}

// ---------------- gather2 + FC fused: writes logits directly ----------------
__global__ void k_gather_fc(const float* __restrict__ b,
                            const float* __restrict__ Wfc,
                            const float* __restrict__ bfc,
                            float* __restrict__ out) {
    __shared__ float WsT[NC * HID];
    __shared__ float bs[NC];
    for (int i = threadIdx.x; i < NC * HID; i += blockDim.x) {
        int c = i >> 7;
        int k = i & 127;
        WsT[i] = Wfc[k * NC + c];
    }
    if (threadIdx.x < NC) bs[threadIdx.x] = bfc[threadIdx.x];
    __syncthreads();

    const int lane = threadIdx.x & 31;
    int node = blockIdx.x * (blockDim.x >> 5) + (threadIdx.x >> 5);
    if (node >= NN) return;
    float4 a = gather_node(node, lane, b);

#pragma unroll
    for (int c = 0; c < NC; c++) {
        const float4 w = reinterpret_cast<const float4*>(WsT + c * HID)[lane];
        float p = a.x * w.x + a.y * w.y + a.z * w.z + a.w * w.w;
        p += __shfl_xor_sync(0xffffffffu, p, 16);
        p += __shfl_xor_sync(0xffffffffu, p, 8);
        p += __shfl_xor_sync(0xffffffffu, p, 4);
        p += __shfl_xor_sync(0xffffffffu, p, 2);
        p += __shfl_xor_sync(0xffffffffu, p, 1);
        if (lane == 0) out[node * NC + c] = p + bs[c];
    }
}

// ---------------- launch ----------------
extern "C" void kernel_launch(void* const* d_in, const int* in_sizes, int n_in,
                              void* d_out, int out_size) {
    const float* x  = (const float*)d_in[0];
    const int* ei   = (const int*)d_in[1];   // int32 (JAX x64 disabled)
    const float* W1 = (const float*)d_in[2];
    const float* b1 = (const float*)d_in[3];
    const float* W2 = (const float*)d_in[4];
    const float* b2 = (const float*)d_in[5];
    const float* Wfc = (const float*)d_in[6];
    const float* bfc = (const float*)d_in[7];
    float* out = (float*)d_out;

    static cudaStream_t s2 = nullptr;
    static cudaEvent_t evFork = nullptr, evJoin = nullptr;
    if (!s2) {
        cudaStreamCreate(&s2);
        cudaEventCreateWithFlags(&evFork, cudaEventDisableTiming);
        cudaEventCreateWithFlags(&evJoin, cudaEventDisableTiming);
    }

    const int T = 256;
    const int eBlk2 = (EE / 2 + T - 1) / T;      // 1172
    const int gemmBlocks = (NN + BM - 1) / BM;   // 391
    const int warpBlocks = (NN + 7) / 8;

    // fork: GEMM1 (independent of graph structure) on side stream
    cudaEventRecord(evFork, 0);
    cudaStreamWaitEvent(s2, evFork, 0);
    k_gemm_fp16<<<gemmBlocks, 256, 0, s2>>>(x, W1);

    // CSR build chain on main stream (concurrent with GEMM1)
    k_deg_count<<<eBlk2, T>>>(ei);
    k_scan<<<NB, SCAN_T>>>();
    k_bin<<<eBlk2, T>>>(ei);

    // join
    cudaEventRecord(evJoin, s2);
    cudaStreamWaitEvent(0, evJoin, 0);

    // conv1 aggregate -> GEMM2 (fp16 A path) -> fused conv2-aggregate+FC
    k_gather<<<warpBlocks, T>>>(b1);
    k_gemm_fp16<<<gemmBlocks, 256>>>(nullptr, W2);
    k_gather_fc<<<warpBlocks, T>>>(b2, Wfc, bfc, out);
}